// round 1
// baseline (speedup 1.0000x reference)
#include <cuda_runtime.h>
#include <cuda_bf16.h>
#include <math.h>

#define NB    4096
#define PAD   (NB / 2)
#define BATCH 8192
#define THREADS 512
#define NWARP (THREADS / 32)

// Precomputed per-bank probability p = sigmoid(logits), and the constant
// C = sum_j log_sigmoid(-logits[j]).
__device__ float g_p[NB];
__device__ float g_C;

// ---------------------------------------------------------------------------
// Precompute kernel: single block. Fills g_p and g_C.
// ---------------------------------------------------------------------------
__global__ void precompute_kernel(const float* __restrict__ logits) {
    __shared__ float s_red[NWARP];
    const int tid = threadIdx.x;
    float acc = 0.0f;

    #pragma unroll
    for (int j = tid; j < NB; j += THREADS) {
        float l = logits[j];
        // p = sigmoid(l)
        g_p[j] = 1.0f / (1.0f + expf(-l));
        // log_sigmoid(-l) = -log(1 + e^{l}) ; stable form:
        // = -(log1p(exp(-|l|)) + max(l, 0))
        float a = fabsf(l);
        acc -= log1pf(expf(-a)) + fmaxf(l, 0.0f);
    }

    // warp reduce
    #pragma unroll
    for (int off = 16; off > 0; off >>= 1)
        acc += __shfl_xor_sync(0xFFFFFFFFu, acc, off);
    if ((tid & 31) == 0) s_red[tid >> 5] = acc;
    __syncthreads();
    if (tid < 32) {
        float v = (tid < NWARP) ? s_red[tid] : 0.0f;
        #pragma unroll
        for (int off = 16; off > 0; off >>= 1)
            v += __shfl_xor_sync(0xFFFFFFFFu, v, off);
        if (tid == 0) g_C = v;
    }
}

// ---------------------------------------------------------------------------
// Main fused kernel: one CTA per batch row.
//   1. read u row (float4), grid = (u < p), acc += grid * l, grid -> smem
//   2. block-reduce acc ; log_probs[b] = C + acc
//   3. gather reflect-shifted window from smem -> masks row (coalesced)
// ---------------------------------------------------------------------------
__global__ __launch_bounds__(THREADS)
void filterbank_mask_kernel(const float* __restrict__ logits,
                            const float* __restrict__ u,
                            const int*   __restrict__ shift,
                            float*       __restrict__ masks,
                            float*       __restrict__ log_probs) {
    __shared__ float s_grid[NB];
    __shared__ float s_red[NWARP];

    const int b   = blockIdx.x;
    const int tid = threadIdx.x;

    const float4* __restrict__ u4 = (const float4*)(u + (size_t)b * NB);
    const float4* __restrict__ p4 = (const float4*)g_p;
    const float4* __restrict__ l4 = (const float4*)logits;
    float4* __restrict__ sg4 = (float4*)s_grid;

    float acc = 0.0f;
    // NB/4 = 1024 float4s, 512 threads -> 2 iterations
    #pragma unroll
    for (int it = 0; it < (NB / 4) / THREADS; ++it) {
        const int v = tid + it * THREADS;
        float4 uu = u4[v];
        float4 pp = p4[v];
        float4 ll = l4[v];
        float g0 = (uu.x < pp.x) ? 1.0f : 0.0f;
        float g1 = (uu.y < pp.y) ? 1.0f : 0.0f;
        float g2 = (uu.z < pp.z) ? 1.0f : 0.0f;
        float g3 = (uu.w < pp.w) ? 1.0f : 0.0f;
        acc += g0 * ll.x + g1 * ll.y + g2 * ll.z + g3 * ll.w;
        float4 gg; gg.x = g0; gg.y = g1; gg.z = g2; gg.w = g3;
        sg4[v] = gg;
    }

    // block reduction of acc
    #pragma unroll
    for (int off = 16; off > 0; off >>= 1)
        acc += __shfl_xor_sync(0xFFFFFFFFu, acc, off);
    if ((tid & 31) == 0) s_red[tid >> 5] = acc;
    __syncthreads();
    if (tid < 32) {
        float v = (tid < NWARP) ? s_red[tid] : 0.0f;
        #pragma unroll
        for (int off = 16; off > 0; off >>= 1)
            v += __shfl_xor_sync(0xFFFFFFFFu, v, off);
        if (tid == 0) log_probs[b] = v + g_C;
    }

    // s_grid fully written (the __syncthreads above also covers it)
    const int sh = shift[b];
    float* __restrict__ out = masks + (size_t)b * NB;

    #pragma unroll
    for (int it = 0; it < NB / THREADS; ++it) {
        const int j = tid + it * THREADS;
        int s = sh + j - PAD;               // in [-PAD, NB+PAD-1]
        s = (s < 0) ? -s : s;               // reflect left
        s = (s >= NB) ? (2 * (NB - 1) - s) : s;  // reflect right
        out[j] = s_grid[s];
    }
}

// ---------------------------------------------------------------------------
extern "C" void kernel_launch(void* const* d_in, const int* in_sizes, int n_in,
                              void* d_out, int out_size) {
    const float* logits = (const float*)d_in[0];   // (NB,)
    const float* u      = (const float*)d_in[1];   // (B, NB)
    const int*   shift  = (const int*)  d_in[2];   // (B,)

    float* masks     = (float*)d_out;                       // (B, 1, NB)
    float* log_probs = (float*)d_out + (size_t)BATCH * NB;  // (B,)

    precompute_kernel<<<1, THREADS>>>(logits);
    filterbank_mask_kernel<<<BATCH, THREADS>>>(logits, u, shift, masks, log_probs);
}